// round 1
// baseline (speedup 1.0000x reference)
#include <cuda_runtime.h>
#include <cuda_bf16.h>
#include <math.h>

// ---------------- scratch (static device arrays; no runtime allocation) ----
__device__ float g_q [2048 * 1024];              // box_feats @ Wq^T
__device__ float g_k [2048 * 1024];              // part_feats @ Wk^T
__device__ float g_pw[2048 * 1024];              // part_feats @ conv_w^T
__device__ float g_L [2048 * 16 * 1024];         // logits / softmax, [n_glob][g][p]

// ---------------- generic tiled SGEMM ------------------------------------
// C[m,n] = alpha * sum_k A[m,k] * (NT ? B[n,k] : B[k,n])  + bias[n]
// batched over blockIdx.z decomposed as (b = z/ngroup, g = z%ngroup) with
// independent strides per (b, g) for A, B, C and a per-g stride for bias.
#define BM 128
#define BN 64
#define BK 16

template <bool NT>
__global__ __launch_bounds__(256) void sgemm_kernel(
    const float* __restrict__ A, const float* __restrict__ B,
    const float* __restrict__ bias, float* __restrict__ C,
    int M, int N, int K, int lda, int ldb, int ldc,
    long long sA1, long long sA2, long long sB1, long long sB2,
    long long sC1, long long sC2, long long sBias2,
    int ngroup, float alpha)
{
    __shared__ float As[BK][BM + 4];
    __shared__ float Bs[BK][BN + 4];

    const int z  = blockIdx.z;
    const int bb = z / ngroup;
    const int gg = z % ngroup;
    A += (size_t)bb * sA1 + (size_t)gg * sA2;
    B += (size_t)bb * sB1 + (size_t)gg * sB2;
    C += (size_t)bb * sC1 + (size_t)gg * sC2;
    if (bias) bias += (size_t)gg * sBias2;

    const int m0  = blockIdx.y * BM;
    const int n0  = blockIdx.x * BN;
    const int tid = threadIdx.x;
    const int tx  = tid & 15;   // 0..15 -> 4 cols each
    const int ty  = tid >> 4;   // 0..15 -> 8 rows each

    float acc[8][4];
#pragma unroll
    for (int i = 0; i < 8; i++)
#pragma unroll
        for (int j = 0; j < 4; j++) acc[i][j] = 0.f;

    for (int kt = 0; kt < K; kt += BK) {
        // load A tile (A is [M,K] row-major; store transposed As[k][m])
#pragma unroll
        for (int r = 0; r < 8; r++) {
            int flat = r * 256 + tid;        // 0..2047
            int m = flat >> 4;
            int k = flat & 15;
            As[k][m] = A[(size_t)(m0 + m) * lda + kt + k];
        }
        // load B tile
#pragma unroll
        for (int r = 0; r < 4; r++) {
            int flat = r * 256 + tid;        // 0..1023
            if (NT) {
                int n = flat >> 4;
                int k = flat & 15;
                Bs[k][n] = B[(size_t)(n0 + n) * ldb + kt + k];
            } else {
                int k = flat / BN;
                int n = flat % BN;
                Bs[k][n] = B[(size_t)(kt + k) * ldb + n0 + n];
            }
        }
        __syncthreads();

#pragma unroll
        for (int kk = 0; kk < BK; kk++) {
            float a[8], bfr[4];
            float4 a0 = *(const float4*)&As[kk][ty * 8];
            float4 a1 = *(const float4*)&As[kk][ty * 8 + 4];
            float4 b0 = *(const float4*)&Bs[kk][tx * 4];
            a[0] = a0.x; a[1] = a0.y; a[2] = a0.z; a[3] = a0.w;
            a[4] = a1.x; a[5] = a1.y; a[6] = a1.z; a[7] = a1.w;
            bfr[0] = b0.x; bfr[1] = b0.y; bfr[2] = b0.z; bfr[3] = b0.w;
#pragma unroll
            for (int i = 0; i < 8; i++)
#pragma unroll
                for (int j = 0; j < 4; j++)
                    acc[i][j] += a[i] * bfr[j];
        }
        __syncthreads();
    }

#pragma unroll
    for (int i = 0; i < 8; i++) {
        int m = m0 + ty * 8 + i;
#pragma unroll
        for (int j = 0; j < 4; j++) {
            int n = n0 + tx * 4 + j;
            float v = alpha * acc[i][j];
            if (bias) v += bias[n];
            C[(size_t)m * ldc + n] = v;
        }
    }
}

// ---------------- position embedding -> Wg -> log, added into L -----------
__global__ __launch_bounds__(256) void poslogit_kernel(
    const float* __restrict__ rois, const float* __restrict__ part_rois,
    const float* __restrict__ Wg_w, const float* __restrict__ Wg_b,
    float* __restrict__ L)
{
    __shared__ float wg[16][64];
    __shared__ float wb[16];
    const int t = threadIdx.x;
    for (int i = t; i < 1024; i += 256) wg[i >> 6][i & 63] = Wg_w[i];
    if (t < 16) wb[t] = Wg_b[t];

    const int b = blockIdx.z;            // half index
    const int n = blockIdx.y;            // box within half
    const int p = blockIdx.x * 256 + t;  // part within half
    const int ng = b * 1024 + n;
    const int pg = b * 1024 + p;

    const float xmin = rois[ng * 5 + 1];
    const float ymin = rois[ng * 5 + 2];
    const float xmax = rois[ng * 5 + 3];
    const float ymax = rois[ng * 5 + 4];
    const float pxmin = part_rois[pg * 5 + 1];
    const float pymin = part_rois[pg * 5 + 2];
    const float pxmax = part_rois[pg * 5 + 3];
    const float pymax = part_rois[pg * 5 + 4];
    __syncthreads();

    const float bw = xmax - xmin + 1.f;
    const float bh = ymax - ymin + 1.f;
    const float pw = pxmax - pxmin + 1.f;
    const float ph = pymax - pymin + 1.f;
    const float cx = 0.5f * (xmin + xmax);
    const float cy = 0.5f * (ymin + ymax);
    const float pcx = 0.5f * (pxmin + pxmax);
    const float pcy = 0.5f * (pymin + pymax);

    float dx = fabsf((cx - pcx) / bw);
    float dy = fabsf((cy - pcy) / bh);
    dx = logf(fmaxf(dx, 1e-3f));
    dy = logf(fmaxf(dy, 1e-3f));
    const float dw = logf(pw / bw);
    const float dh = logf(ph / bh);
    float pos[4] = {dx, dy, dw, dh};

    // 1 / 1000^(j/8)
    const float inv_em[8] = {
        1.0f, 0.42169651f, 0.17782794f, 0.074989424f,
        0.031622777f, 0.013335215f, 0.0056234133f, 0.0023713737f};

    float acc[16];
#pragma unroll
    for (int g = 0; g < 16; g++) acc[g] = wb[g];

#pragma unroll
    for (int i = 0; i < 4; i++) {
        const float pv = 100.f * pos[i];
#pragma unroll
        for (int j = 0; j < 8; j++) {
            float s, c;
            __sincosf(pv * inv_em[j], &s, &c);
#pragma unroll
            for (int g = 0; g < 16; g++)
                acc[g] += s * wg[g][i * 16 + j] + c * wg[g][i * 16 + 8 + j];
        }
    }

    // relu then clamp@1e-6 then log  ==  log(max(x, 1e-6))
    size_t base = ((size_t)ng * 16) * 1024 + p;
#pragma unroll
    for (int g = 0; g < 16; g++) {
        float lw = logf(fmaxf(acc[g], 1e-6f));
        L[base + (size_t)g * 1024] += lw;
    }
}

// ---------------- row softmax over p (rows of length 1024) ----------------
__global__ __launch_bounds__(256) void softmax_kernel(float* __restrict__ L)
{
    __shared__ float red[256];
    const size_t base = (size_t)blockIdx.x * 1024;
    const int t = threadIdx.x;

    float v0 = L[base + t];
    float v1 = L[base + t + 256];
    float v2 = L[base + t + 512];
    float v3 = L[base + t + 768];

    float mx = fmaxf(fmaxf(v0, v1), fmaxf(v2, v3));
    red[t] = mx;
    __syncthreads();
    for (int s = 128; s > 0; s >>= 1) {
        if (t < s) red[t] = fmaxf(red[t], red[t + s]);
        __syncthreads();
    }
    mx = red[0];
    __syncthreads();

    v0 = __expf(v0 - mx);
    v1 = __expf(v1 - mx);
    v2 = __expf(v2 - mx);
    v3 = __expf(v3 - mx);
    red[t] = v0 + v1 + v2 + v3;
    __syncthreads();
    for (int s = 128; s > 0; s >>= 1) {
        if (t < s) red[t] += red[t + s];
        __syncthreads();
    }
    const float inv = 1.f / red[0];

    L[base + t]       = v0 * inv;
    L[base + t + 256] = v1 * inv;
    L[base + t + 512] = v2 * inv;
    L[base + t + 768] = v3 * inv;
}

// ---------------- host launch ---------------------------------------------
extern "C" void kernel_launch(void* const* d_in, const int* in_sizes, int n_in,
                              void* d_out, int out_size)
{
    const float* rois       = (const float*)d_in[0];
    const float* part_rois  = (const float*)d_in[1];
    const float* box_feats  = (const float*)d_in[2];
    const float* part_feats = (const float*)d_in[3];
    const float* Wg_w       = (const float*)d_in[4];
    const float* Wg_b       = (const float*)d_in[5];
    const float* Wq_w       = (const float*)d_in[6];
    const float* Wq_b       = (const float*)d_in[7];
    const float* Wk_w       = (const float*)d_in[8];
    const float* Wk_b       = (const float*)d_in[9];
    const float* conv_w     = (const float*)d_in[10];
    const float* conv_b     = (const float*)d_in[11];
    float* out = (float*)d_out;

    float *q, *k, *pw, *L;
    cudaGetSymbolAddress((void**)&q,  g_q);
    cudaGetSymbolAddress((void**)&k,  g_k);
    cudaGetSymbolAddress((void**)&pw, g_pw);
    cudaGetSymbolAddress((void**)&L,  g_L);

    dim3 blk(256);

    // q = box_feats @ Wq^T + Wq_b        [2048,1024] x [1024,1024]^T
    sgemm_kernel<true><<<dim3(16, 16, 1), blk>>>(
        box_feats, Wq_w, Wq_b, q, 2048, 1024, 1024, 1024, 1024, 1024,
        0, 0, 0, 0, 0, 0, 0, 1, 1.f);

    // k = part_feats @ Wk^T + Wk_b
    sgemm_kernel<true><<<dim3(16, 16, 1), blk>>>(
        part_feats, Wk_w, Wk_b, k, 2048, 1024, 1024, 1024, 1024, 1024,
        0, 0, 0, 0, 0, 0, 0, 1, 1.f);

    // pw = part_feats @ conv_w^T  (bias added in final GEMM)
    sgemm_kernel<true><<<dim3(16, 16, 1), blk>>>(
        part_feats, conv_w, nullptr, pw, 2048, 1024, 1024, 1024, 1024, 1024,
        0, 0, 0, 0, 0, 0, 0, 1, 1.f);

    // att/16 into L: batched over (b,g): [1024,64] x [1024,64]^T -> [1024,1024]
    sgemm_kernel<true><<<dim3(16, 8, 32), blk>>>(
        q, k, nullptr, L, 1024, 1024, 64, 1024, 1024, 16384,
        /*sA1*/ 1048576LL, /*sA2*/ 64LL,
        /*sB1*/ 1048576LL, /*sB2*/ 64LL,
        /*sC1*/ 16777216LL, /*sC2*/ 1024LL, 0LL,
        16, 1.f / 16.f);

    // L += log(att_weight)
    poslogit_kernel<<<dim3(4, 1024, 2), blk>>>(rois, part_rois, Wg_w, Wg_b, L);

    // softmax over p, in place (32768 rows of 1024)
    softmax_kernel<<<32768, blk>>>(L);

    // rel = sm @ PW + conv_b: batched over (b,g): [1024,1024] x [1024,64]
    sgemm_kernel<false><<<dim3(1, 8, 32), blk>>>(
        L, pw, conv_b, out, 1024, 64, 1024, 16384, 1024, 1024,
        /*sA1*/ 16777216LL, /*sA2*/ 1024LL,
        /*sB1*/ 1048576LL, /*sB2*/ 64LL,
        /*sC1*/ 1048576LL, /*sC2*/ 64LL, /*sBias2*/ 64LL,
        16, 1.f);
}

// round 3
// speedup vs baseline: 1.7424x; 1.7424x over previous
#include <cuda_runtime.h>
#include <cuda_bf16.h>
#include <cstdint>
#include <math.h>

// ---------------- scratch -------------------------------------------------
__device__ float g_q [2048 * 1024];      // box_feats @ Wq^T
__device__ float g_k [2048 * 1024];      // part_feats @ Wk^T
__device__ float g_pw[1024 * 2048];      // pwT = conv_w @ part_feats^T  [GE, P]
__device__ float g_L [2048 * 16 * 1024]; // logits / softmax

// ---------------- helpers -------------------------------------------------
__device__ __forceinline__ uint32_t smem_u32(const void* p) {
    uint32_t a;
    asm("{ .reg .u64 t; cvta.to.shared.u64 t, %1; cvt.u32.u64 %0, t; }"
        : "=r"(a) : "l"(p));
    return a;
}
// pack two fp32 into bf16x2: low half = lo, high half = hi
__device__ __forceinline__ uint32_t pack_bf(float lo, float hi) {
    uint32_t r;
    asm("cvt.rn.bf16x2.f32 %0, %1, %2;" : "=r"(r) : "f"(hi), "f"(lo));
    return r;
}
#define STS64(a, x, y) \
    asm volatile("st.shared.v2.b32 [%0], {%1, %2};" :: "r"(a), "r"(x), "r"(y) : "memory")

__device__ __forceinline__ void ldsm4(uint32_t* r, uint32_t addr) {
    asm volatile("ldmatrix.sync.aligned.m8n8.x4.shared.b16 {%0,%1,%2,%3}, [%4];"
        : "=r"(r[0]), "=r"(r[1]), "=r"(r[2]), "=r"(r[3]) : "r"(addr));
}
__device__ __forceinline__ void mma16816(float* d, const uint32_t* a, const uint32_t* b) {
    asm volatile(
        "mma.sync.aligned.m16n8k16.row.col.f32.bf16.bf16.f32 "
        "{%0,%1,%2,%3}, {%4,%5,%6,%7}, {%8,%9}, {%0,%1,%2,%3};"
        : "+f"(d[0]), "+f"(d[1]), "+f"(d[2]), "+f"(d[3])
        : "r"(a[0]), "r"(a[1]), "r"(a[2]), "r"(a[3]), "r"(b[0]), "r"(b[1]));
}

// ---------------- bf16-split tensor-core GEMM -----------------------------
// C[m,n] = alpha * sum_k A[m,k]*B[n,k] + bias[n]  (fp32 in/out, ~fp32 precision)
// BM=128, BN in {64,128}, BK=32 fp32 per mainloop iter.
// SMEM rows padded to 80B (32 bf16 + 16B pad) -> ldmatrix conflict-free.
template <int BN>
__global__ __launch_bounds__(256) void tgemm(
    const float* __restrict__ A, const float* __restrict__ B,
    const float* __restrict__ bias, float* __restrict__ C,
    int K, int lda, int ldb, int ldc,
    long long sA1, long long sA2, long long sB1, long long sB2,
    long long sC1, long long sC2, long long sBias2,
    int ngroup, float alpha)
{
    constexpr int WGM = (BN == 128) ? 4 : 8;
    constexpr int WGN = (BN == 128) ? 2 : 1;
    constexpr int WTM = 128 / WGM;          // 32 or 16
    constexpr int WTN = BN / WGN;           // 64
    constexpr int MB  = WTM / 16;           // 2 or 1
    constexpr int NB  = WTN / 8;            // 8
    constexpr int NB2 = WTN / 16;           // 4
    constexpr int A_MAT = 128 * 80;
    constexpr int B_MAT = BN * 80;
    constexpr int BUFSZ = 2 * A_MAT + 2 * B_MAT;
    constexpr int NB4B = BN / 32;           // float4 LDGs per thread for B

    extern __shared__ char smem[];
    const uint32_t sb = smem_u32(smem);

    const int t = threadIdx.x;
    const int wid = t >> 5, lane = t & 31;
    const int wm = wid % WGM, wn = wid / WGM;

    const int z = blockIdx.z;
    const int bb = z / ngroup;
    const int gg = z - bb * ngroup;
    A += bb * sA1 + gg * sA2;
    B += bb * sB1 + gg * sB2;
    C += bb * sC1 + gg * sC2;
    if (bias) bias += gg * sBias2;

    const int m0 = blockIdx.y * 128;
    const int n0 = blockIdx.x * BN;

    float4 pa[4];
    float4 pb[NB4B];

    auto ldgA = [&](int c) {
        const int k0 = c * 32;
#pragma unroll
        for (int r = 0; r < 4; r++) {
            int f = r * 256 + t, row = f >> 3, seg = f & 7;
            pa[r] = *(const float4*)(A + (size_t)(m0 + row) * lda + k0 + seg * 4);
        }
    };
    auto ldgB = [&](int c) {
        const int k0 = c * 32;
#pragma unroll
        for (int r = 0; r < NB4B; r++) {
            int f = r * 256 + t, row = f >> 3, seg = f & 7;
            pb[r] = *(const float4*)(B + (size_t)(n0 + row) * ldb + k0 + seg * 4);
        }
    };
    auto sts = [&](int buf) {
        const uint32_t base = sb + buf * BUFSZ;
#pragma unroll
        for (int r = 0; r < 4; r++) {
            int f = r * 256 + t, row = f >> 3, seg = f & 7;
            float4 v = pa[r];
            uint32_t h01 = pack_bf(v.x, v.y);
            uint32_t h23 = pack_bf(v.z, v.w);
            float hx = __uint_as_float(h01 << 16);
            float hy = __uint_as_float(h01 & 0xFFFF0000u);
            float hz = __uint_as_float(h23 << 16);
            float hw = __uint_as_float(h23 & 0xFFFF0000u);
            uint32_t l01 = pack_bf(v.x - hx, v.y - hy);
            uint32_t l23 = pack_bf(v.z - hz, v.w - hw);
            uint32_t off = base + row * 80 + seg * 8;
            STS64(off, h01, h23);
            STS64(off + A_MAT, l01, l23);
        }
#pragma unroll
        for (int r = 0; r < NB4B; r++) {
            int f = r * 256 + t, row = f >> 3, seg = f & 7;
            float4 v = pb[r];
            uint32_t h01 = pack_bf(v.x, v.y);
            uint32_t h23 = pack_bf(v.z, v.w);
            float hx = __uint_as_float(h01 << 16);
            float hy = __uint_as_float(h01 & 0xFFFF0000u);
            float hz = __uint_as_float(h23 << 16);
            float hw = __uint_as_float(h23 & 0xFFFF0000u);
            uint32_t l01 = pack_bf(v.x - hx, v.y - hy);
            uint32_t l23 = pack_bf(v.z - hz, v.w - hw);
            uint32_t off = base + 2 * A_MAT + row * 80 + seg * 8;
            STS64(off, h01, h23);
            STS64(off + B_MAT, l01, l23);
        }
    };

    float acc[MB][NB][4];
#pragma unroll
    for (int i = 0; i < MB; i++)
#pragma unroll
        for (int j = 0; j < NB; j++)
#pragma unroll
            for (int q = 0; q < 4; q++) acc[i][j][q] = 0.f;

    // ldmatrix per-lane address offsets
    const uint32_t a_lane = (uint32_t)((lane & 15) * 80 + (lane >> 4) * 16);
    const uint32_t b_lane = (uint32_t)(((lane & 7) + ((lane >> 4) << 3)) * 80
                                       + ((lane >> 3) & 1) * 16);

    auto compute = [&](int buf) {
        const uint32_t base = sb + buf * BUFSZ;
#pragma unroll
        for (int ks = 0; ks < 2; ks++) {
            const uint32_t ko = ks * 32;
            uint32_t Ah[MB][4], Al[MB][4], Bh[NB][2], Bl[NB][2];
#pragma unroll
            for (int mb = 0; mb < MB; mb++) {
                uint32_t ad = base + (wm * WTM + mb * 16) * 80 + a_lane + ko;
                ldsm4(Ah[mb], ad);
                ldsm4(Al[mb], ad + A_MAT);
            }
#pragma unroll
            for (int n2 = 0; n2 < NB2; n2++) {
                uint32_t bd = base + 2 * A_MAT + (wn * WTN + n2 * 16) * 80 + b_lane + ko;
                ldsm4(&Bh[2 * n2][0], bd);
                ldsm4(&Bl[2 * n2][0], bd + B_MAT);
            }
#pragma unroll
            for (int mb = 0; mb < MB; mb++)
#pragma unroll
                for (int nb = 0; nb < NB; nb++) {
                    mma16816(acc[mb][nb], Ah[mb], Bh[nb]);
                    mma16816(acc[mb][nb], Ah[mb], Bl[nb]);
                    mma16816(acc[mb][nb], Al[mb], Bh[nb]);
                }
        }
    };

    const int NC = K >> 5;
    ldgA(0); ldgB(0);
    sts(0);
    if (NC > 1) { ldgA(1); ldgB(1); }
    __syncthreads();

    for (int c = 0; c < NC; c++) {
        compute(c & 1);
        __syncthreads();
        if (c + 1 < NC) {
            sts((c + 1) & 1);
            __syncthreads();
            if (c + 2 < NC) { ldgA(c + 2); ldgB(c + 2); }
        }
    }

    // epilogue: accum regs -> gmem
    const int er = lane >> 2, ec = (lane & 3) * 2;
#pragma unroll
    for (int mb = 0; mb < MB; mb++) {
#pragma unroll
        for (int nb = 0; nb < NB; nb++) {
            const int m = m0 + wm * WTM + mb * 16 + er;
            const int n = n0 + wn * WTN + nb * 8 + ec;
            float b0 = 0.f, b1 = 0.f;
            if (bias) { b0 = bias[n]; b1 = bias[n + 1]; }
            float2 v0, v1;
            v0.x = alpha * acc[mb][nb][0] + b0;
            v0.y = alpha * acc[mb][nb][1] + b1;
            v1.x = alpha * acc[mb][nb][2] + b0;
            v1.y = alpha * acc[mb][nb][3] + b1;
            *(float2*)(C + (size_t)m * ldc + n) = v0;
            *(float2*)(C + (size_t)(m + 8) * ldc + n) = v1;
        }
    }
}

// ---------------- position embedding -> Wg -> log, added into L -----------
__global__ __launch_bounds__(256) void poslogit_kernel(
    const float* __restrict__ rois, const float* __restrict__ part_rois,
    const float* __restrict__ Wg_w, const float* __restrict__ Wg_b,
    float* __restrict__ L)
{
    __shared__ float wg[16][64];
    __shared__ float wb[16];
    const int t = threadIdx.x;
    for (int i = t; i < 1024; i += 256) wg[i >> 6][i & 63] = Wg_w[i];
    if (t < 16) wb[t] = Wg_b[t];

    const int b = blockIdx.z;
    const int n = blockIdx.y;
    const int p = blockIdx.x * 256 + t;
    const int ng = b * 1024 + n;
    const int pg = b * 1024 + p;

    const float xmin = rois[ng * 5 + 1];
    const float ymin = rois[ng * 5 + 2];
    const float xmax = rois[ng * 5 + 3];
    const float ymax = rois[ng * 5 + 4];
    const float pxmin = part_rois[pg * 5 + 1];
    const float pymin = part_rois[pg * 5 + 2];
    const float pxmax = part_rois[pg * 5 + 3];
    const float pymax = part_rois[pg * 5 + 4];
    __syncthreads();

    const float bw = xmax - xmin + 1.f;
    const float bh = ymax - ymin + 1.f;
    const float pw = pxmax - pxmin + 1.f;
    const float ph = pymax - pymin + 1.f;
    const float cx = 0.5f * (xmin + xmax);
    const float cy = 0.5f * (ymin + ymax);
    const float pcx = 0.5f * (pxmin + pxmax);
    const float pcy = 0.5f * (pymin + pymax);

    float dx = fabsf((cx - pcx) / bw);
    float dy = fabsf((cy - pcy) / bh);
    dx = logf(fmaxf(dx, 1e-3f));
    dy = logf(fmaxf(dy, 1e-3f));
    const float dw = logf(pw / bw);
    const float dh = logf(ph / bh);
    float pos[4] = {dx, dy, dw, dh};

    const float inv_em[8] = {
        1.0f, 0.42169651f, 0.17782794f, 0.074989424f,
        0.031622777f, 0.013335215f, 0.0056234133f, 0.0023713737f};

    float acc[16];
#pragma unroll
    for (int g = 0; g < 16; g++) acc[g] = wb[g];

#pragma unroll
    for (int i = 0; i < 4; i++) {
        const float pv = 100.f * pos[i];
#pragma unroll
        for (int j = 0; j < 8; j++) {
            float s, c;
            __sincosf(pv * inv_em[j], &s, &c);
#pragma unroll
            for (int g = 0; g < 16; g++)
                acc[g] += s * wg[g][i * 16 + j] + c * wg[g][i * 16 + 8 + j];
        }
    }

    size_t base = ((size_t)ng * 16) * 1024 + p;
#pragma unroll
    for (int g = 0; g < 16; g++) {
        float lw = logf(fmaxf(acc[g], 1e-6f));
        L[base + (size_t)g * 1024] += lw;
    }
}

// ---------------- row softmax over p --------------------------------------
__global__ __launch_bounds__(256) void softmax_kernel(float* __restrict__ L)
{
    __shared__ float red[256];
    const size_t base = (size_t)blockIdx.x * 1024;
    const int t = threadIdx.x;

    float v0 = L[base + t];
    float v1 = L[base + t + 256];
    float v2 = L[base + t + 512];
    float v3 = L[base + t + 768];

    float mx = fmaxf(fmaxf(v0, v1), fmaxf(v2, v3));
    red[t] = mx;
    __syncthreads();
    for (int s = 128; s > 0; s >>= 1) {
        if (t < s) red[t] = fmaxf(red[t], red[t + s]);
        __syncthreads();
    }
    mx = red[0];
    __syncthreads();

    v0 = __expf(v0 - mx);
    v1 = __expf(v1 - mx);
    v2 = __expf(v2 - mx);
    v3 = __expf(v3 - mx);
    red[t] = v0 + v1 + v2 + v3;
    __syncthreads();
    for (int s = 128; s > 0; s >>= 1) {
        if (t < s) red[t] += red[t + s];
        __syncthreads();
    }
    const float inv = 1.f / red[0];

    L[base + t]       = v0 * inv;
    L[base + t + 256] = v1 * inv;
    L[base + t + 512] = v2 * inv;
    L[base + t + 768] = v3 * inv;
}

// ---------------- host ----------------------------------------------------
extern "C" void kernel_launch(void* const* d_in, const int* in_sizes, int n_in,
                              void* d_out, int out_size)
{
    const float* rois       = (const float*)d_in[0];
    const float* part_rois  = (const float*)d_in[1];
    const float* box_feats  = (const float*)d_in[2];
    const float* part_feats = (const float*)d_in[3];
    const float* Wg_w       = (const float*)d_in[4];
    const float* Wg_b       = (const float*)d_in[5];
    const float* Wq_w       = (const float*)d_in[6];
    const float* Wq_b       = (const float*)d_in[7];
    const float* Wk_w       = (const float*)d_in[8];
    const float* Wk_b       = (const float*)d_in[9];
    const float* conv_w     = (const float*)d_in[10];
    const float* conv_b     = (const float*)d_in[11];
    float* out = (float*)d_out;

    float *q, *k, *pw, *L;
    cudaGetSymbolAddress((void**)&q,  g_q);
    cudaGetSymbolAddress((void**)&k,  g_k);
    cudaGetSymbolAddress((void**)&pw, g_pw);
    cudaGetSymbolAddress((void**)&L,  g_L);

    // smem: double buffer of (A hi/lo + B hi/lo), 80B rows
    const int SM128 = 2 * (2 * 128 * 80 + 2 * 128 * 80); // 81920
    const int SM64  = 2 * (2 * 128 * 80 + 2 * 64 * 80);  // 61440
    static bool attr_done = false;
    if (!attr_done) {
        cudaFuncSetAttribute(tgemm<128>, cudaFuncAttributeMaxDynamicSharedMemorySize, SM128);
        cudaFuncSetAttribute(tgemm<64>,  cudaFuncAttributeMaxDynamicSharedMemorySize, SM64);
        attr_done = true;
    }

    // q = box_feats @ Wq^T + Wq_b         M=2048 N=1024 K=1024
    tgemm<128><<<dim3(8, 16, 1), 256, SM128>>>(
        box_feats, Wq_w, Wq_b, q, 1024, 1024, 1024, 1024,
        0, 0, 0, 0, 0, 0, 0, 1, 1.f);

    // k = part_feats @ Wk^T + Wk_b
    tgemm<128><<<dim3(8, 16, 1), 256, SM128>>>(
        part_feats, Wk_w, Wk_b, k, 1024, 1024, 1024, 1024,
        0, 0, 0, 0, 0, 0, 0, 1, 1.f);

    // pwT = conv_w @ part_feats^T         M=1024 N=2048 K=1024  -> [GE, P]
    tgemm<128><<<dim3(16, 8, 1), 256, SM128>>>(
        conv_w, part_feats, nullptr, pw, 1024, 1024, 1024, 2048,
        0, 0, 0, 0, 0, 0, 0, 1, 1.f);

    // att/16 into L: 32 batches (b,g): M=1024 N=1024 K=64
    tgemm<128><<<dim3(8, 8, 32), 256, SM128>>>(
        q, k, nullptr, L, 64, 1024, 1024, 16384,
        1048576LL, 64LL, 1048576LL, 64LL,
        16777216LL, 1024LL, 0LL, 16, 1.f / 16.f);

    // L += log(att_weight)
    poslogit_kernel<<<dim3(4, 1024, 2), 256>>>(rois, part_rois, Wg_w, Wg_b, L);

    // softmax over p
    softmax_kernel<<<32768, 256>>>(L);

    // rel = sm @ pwT^T + conv_b: 32 batches: M=1024 N=64 K=1024
    tgemm<64><<<dim3(1, 8, 32), 256, SM64>>>(
        L, pw, conv_b, out, 1024, 16384, 2048, 1024,
        16777216LL, 1024LL, 1024LL, 131072LL,
        1048576LL, 64LL, 64LL, 16, 1.f);
}